// round 13
// baseline (speedup 1.0000x reference)
#include <cuda_runtime.h>
#include <cstdint>

#define BATCH 65536
#define INP 64
#define HID 128
#define NACT 16
#define BM 64
#define NTHR 512

// smem strides (floats); all ≡ 4 (mod 32) -> conflict-free LDSM row addressing
#define XS 68
#define HS 132
#define WS 36
#define WHS 132

// Layout (floats): sH [64x132] at 0 (sX [64x68] ALIASED; x dead after superchunk 1),
// 3-buffer gate-fused weight ring [384x36] each, head weights, biases.
#define RING_OFF 8448
#define BUF_FLOATS (384 * WS)                   // 13824
#define WH_OFF (RING_OFF + 3 * BUF_FLOATS)      // 49920
#define SB_OFF (WH_OFF + 24 * WHS)              // 53088
#define SMEM_FLOATS (SB_OFF + 6 * 128)          // 53856
#define SMEM_BYTES (SMEM_FLOATS * 4)            // 215424 B -> 1 CTA/SM

__device__ __forceinline__ void cpa16(float* dst, const float* src) {
    unsigned u = (unsigned)__cvta_generic_to_shared(dst);
    asm volatile("cp.async.cg.shared.global [%0], [%1], 16;" ::"r"(u), "l"(src));
}
__device__ __forceinline__ void cpcommit() { asm volatile("cp.async.commit_group;"); }

__device__ __forceinline__ float htanh(float v) {
    float r;
    asm("tanh.approx.f32 %0, %1;" : "=f"(r) : "f"(v));
    return r;
}
__device__ __forceinline__ float fsig(float v) {
    return fmaf(htanh(0.5f * v), 0.5f, 0.5f);
}

#define MMA_TF32(d, a0, a1, a2, a3, b0, b1)                                     \
    asm volatile(                                                               \
        "mma.sync.aligned.m16n8k8.row.col.f32.tf32.tf32.f32 "                   \
        "{%0,%1,%2,%3},{%4,%5,%6,%7},{%8,%9},{%0,%1,%2,%3};"                    \
        : "+f"(d[0]), "+f"(d[1]), "+f"(d[2]), "+f"(d[3])                        \
        : "r"(a0), "r"(a1), "r"(a2), "r"(a3), "r"(b0), "r"(b1))

__device__ __forceinline__ void ldsm4(unsigned r[4], unsigned addr) {
    asm volatile("ldmatrix.sync.aligned.m8n8.x4.shared.b16 {%0,%1,%2,%3}, [%4];"
                 : "=r"(r[0]), "=r"(r[1]), "=r"(r[2]), "=r"(r[3])
                 : "r"(addr));
}
__device__ __forceinline__ void ldsm2(unsigned& r0, unsigned& r1, unsigned addr) {
    asm volatile("ldmatrix.sync.aligned.m8n8.x2.shared.b16 {%0,%1}, [%2];"
                 : "=r"(r0), "=r"(r1)
                 : "r"(addr));
}

__global__ void __launch_bounds__(NTHR, 1)
lstm_policy_kernel(const float* __restrict__ x,
                   const float* __restrict__ Wih0,
                   const float* __restrict__ bih0,
                   const float* __restrict__ bhh0,
                   const float* __restrict__ Wih1,
                   const float* __restrict__ bih1,
                   const float* __restrict__ bhh1,
                   const float* __restrict__ Wp,
                   const float* __restrict__ bp,
                   const float* __restrict__ Wv,
                   const float* __restrict__ bv,
                   float* __restrict__ out) {
    extern __shared__ float sm[];
    float* sH = sm;              // [64][132] h0
    float* sX = sm;              // [64][68]  x, ALIASED (dead after superchunk 1)
    float* sW = sm + RING_OFF;   // 3 x [384][36] ring
    float* sH1 = sm + RING_OFF;  // h1 plain [64][132] over dead ring buf0
    float* sWH = sm + WH_OFF;
    float* sB = sm + SB_OFF;

    const int tid = threadIdx.x;
    const int wid = tid >> 5, lane = tid & 31;
    const int g = lane >> 2, tg = lane & 3;
    // 16 warps, each owns a UNIQUE 8-out-col strip; warp tile 64 rows x 8 cols x 3 gates
    const int ncolW = wid * 8;
    const int rowbase = blockIdx.x * BM;

    // warp-private slab prefetch for superchunk k: 3 gates x 8 rows x 32 K = 192 f4.
    // Only THIS warp reads these rows -> per-warp wait_group; NO block barriers.
    auto prefSlab = [&](int k) {
        const float* W = (k < 2) ? Wih0 : Wih1;
        int ld = (k < 2) ? INP : HID;
        int koff = ((k < 2) ? k : (k - 2)) * 32;
        float* dst = sW + (k % 3) * BUF_FLOATS;
#pragma unroll
        for (int i = 0; i < 6; i++) {
            int idx = lane + i * 32;   // 192 f4
            int gate = idx >> 6;
            int rem = idx & 63;
            int r = rem >> 3, c4 = rem & 7;
            int gbase = (gate == 0) ? 0 : (gate == 1 ? 256 : 384);
            int row = ncolW + r;
            cpa16(dst + (gate * 128 + row) * WS + c4 * 4,
                  W + (size_t)(gbase + row) * ld + koff + c4 * 4);
        }
    };

    // ---- prologue: G0 = {x, head weights}; G1 = {slab0}; G2 = {slab1} ----
    {
        const float* xs = x + (size_t)rowbase * INP;
#pragma unroll
        for (int i = 0; i < 2; i++) {
            int idx = tid + i * NTHR;  // 1024 f4 (64 rows x 16)
            int r = idx >> 4;
            int c4 = idx & 15;
            cpa16(sX + r * XS + c4 * 4, xs + r * INP + c4 * 4);
        }
#pragma unroll
        for (int idx = tid; idx < 544; idx += NTHR) {  // strided! (R2 lesson)
            int r = idx >> 5, c4 = idx & 31;
            const float* srcp = (r < 16) ? (Wp + r * HID + c4 * 4) : (Wv + c4 * 4);
            cpa16(sWH + r * WHS + c4 * 4, srcp);
        }
        cpcommit();      // G0
        prefSlab(0);
        cpcommit();      // G1
        prefSlab(1);
        cpcommit();      // G2
    }

    // combined biases + zero-pad head rows 17..23
    if (tid < 128) {
        sB[tid] = bih0[tid] + bhh0[tid];
        sB[128 + tid] = bih0[256 + tid] + bhh0[256 + tid];
        sB[256 + tid] = bih0[384 + tid] + bhh0[384 + tid];
        sB[384 + tid] = bih1[tid] + bhh1[tid];
        sB[512 + tid] = bih1[256 + tid] + bhh1[256 + tid];
        sB[640 + tid] = bih1[384 + tid] + bhh1[384 + tid];
    }
#pragma unroll
    for (int idx = tid; idx < 7 * HID; idx += NTHR) {
        int r = 17 + idx / HID, c = idx % HID;
        sWH[r * WHS + c] = 0.f;
    }

    asm volatile("cp.async.wait_group 2;");  // G0 done (x, sWH)
    __syncthreads();  // BARRIER 1: x/sB/sWH visible

    // ---- LDSM addresses (same verified mapping; mrow = 0, all warps cover 64 rows) ----
    const int j8 = lane & 7, sel = lane >> 3;
    const int arow = ((sel & 1) << 3) + j8;
    const int acol = (sel >> 1) << 2;
    const unsigned shBase = (unsigned)__cvta_generic_to_shared(sm);
    const unsigned swBase = shBase + RING_OFF * 4;
    const unsigned aX = shBase + (arow * XS + acol) * 4;
    const unsigned aH = shBase + (arow * HS + acol) * 4;
    // B via ldsm.x2: tile0 = K+0..3 (b0), tile1 = K+4..7 (b1); row addr = out-col j8
    const unsigned bO2 = ((ncolW + j8) * WS + ((sel & 1) << 2)) * 4;

    // gate-fused accumulators: [gate][mt][ci], warp tile 64 rows x 8 cols
    float acc[3][4][4];
#pragma unroll
    for (int gt = 0; gt < 3; gt++)
#pragma unroll
        for (int mt = 0; mt < 4; mt++)
#pragma unroll
            for (int ci = 0; ci < 4; ci++) acc[gt][mt][ci] = 0.f;

    // one gate-fused superchunk (K=32): 16 A-ldsm4 (loaded once, reused by all
    // 3 gates) + 12 B-ldsm2 + 48 MMA
    auto gemmChunk = [&](unsigned aBase, unsigned pitch, unsigned wbase) {
#pragma unroll
        for (int ks = 0; ks < 4; ks++) {
            unsigned af[4][4];
#pragma unroll
            for (int mt = 0; mt < 4; mt++) ldsm4(af[mt], aBase + mt * pitch + ks * 32);
#pragma unroll
            for (int gt = 0; gt < 3; gt++) {
                unsigned b0, b1;
                ldsm2(b0, b1, wbase + gt * (128 * WS * 4) + bO2 + ks * 32);
#pragma unroll
                for (int mt = 0; mt < 4; mt++)
                    MMA_TF32(acc[gt][mt], af[mt][0], af[mt][1], af[mt][2], af[mt][3], b0, b1);
            }
        }
    };

    // single-pass epilogue from the 3 gate accs; cols = ncolW + tg*2 + (ci&1)
    auto epi = [&](int L) {
#pragma unroll
        for (int mt = 0; mt < 4; mt++)
#pragma unroll
            for (int ci = 0; ci < 4; ci++) {
                int row = mt * 16 + g + ((ci >> 1) << 3);
                int cc = ncolW + (tg << 1) + (ci & 1);
                float iv = acc[0][mt][ci] + sB[L * 384 + cc];
                float gv = acc[1][mt][ci] + sB[L * 384 + 128 + cc];
                float ov = acc[2][mt][ci] + sB[L * 384 + 256 + cc];
                float h = fsig(ov) * htanh(fsig(iv) * htanh(gv));
                if (L == 0)
                    sH[row * HS + cc] = h;
                else
                    sH1[row * HS + cc] = h;
                acc[0][mt][ci] = 0.f;
                acc[1][mt][ci] = 0.f;
                acc[2][mt][ci] = 0.f;
            }
    };

    const unsigned pX = 16 * XS * 4, pH = 16 * HS * 4;
    const unsigned b0a = swBase, b1a = swBase + BUF_FLOATS * 4, b2a = swBase + 2 * BUF_FLOATS * 4;

    // ---- L0 (K=64: superchunks 0,1 read sX); NO barriers in weight loop ----
    asm volatile("cp.async.wait_group 1;");  // slab0 ready (per-warp)
    prefSlab(2);
    cpcommit();  // G3 -> buf2
    gemmChunk(aX, pX, b0a);
    asm volatile("cp.async.wait_group 1;");  // slab1 ready
    prefSlab(3);
    cpcommit();  // G4 -> buf0 (this warp finished buf0 reads at gemm(0))
    gemmChunk(aX + 128, pX, b1a);

    // ---- layer boundary: h0 overwrites aliased sX ----
    __syncthreads();  // BARRIER 2: all warps done reading x
    epi(0);           // h0 -> sH (own 8 cols)
    __syncthreads();  // BARRIER 3: h0 visible to all warps

    // ---- L1 (K=128: superchunks 2..5 read sH) ----
    asm volatile("cp.async.wait_group 1;");  // slab2 ready
    prefSlab(4);
    cpcommit();  // G5 -> buf1
    gemmChunk(aH, pH, b2a);
    asm volatile("cp.async.wait_group 1;");  // slab3 ready
    prefSlab(5);
    cpcommit();  // G6 -> buf2
    gemmChunk(aH + 128, pH, b0a);
    asm volatile("cp.async.wait_group 1;");  // slab4 ready
    gemmChunk(aH + 256, pH, b1a);
    asm volatile("cp.async.wait_group 0;");  // slab5 ready
    gemmChunk(aH + 384, pH, b2a);

    __syncthreads();  // BARRIER 4: ALL warps done with all buf0 reads (h1 overwrites it)
    epi(1);           // h1 -> plain [64][132] over dead ring buf0
    __syncthreads();  // BARRIER 5: h1 visible

    // ---- heads on tensor cores (warps 0..3; proven code) ----
    float* pol = out;
    float* val = out + (size_t)BATCH * NACT;
    if (wid < 4) {
        float ha[3][4];
#pragma unroll
        for (int nt = 0; nt < 3; nt++)
#pragma unroll
            for (int ci = 0; ci < 4; ci++) ha[nt][ci] = 0.f;
        const unsigned* uA = (const unsigned*)sH1;
        const unsigned* uW = (const unsigned*)sWH;
        const int mrowH = wid * 16;
#pragma unroll
        for (int ks = 0; ks < 16; ks++) {
            const unsigned* bA = uA + (mrowH + g) * HS + ks * 8 + tg;
            unsigned a0 = bA[0], a1 = bA[8 * HS], a2 = bA[4], a3 = bA[8 * HS + 4];
#pragma unroll
            for (int nt = 0; nt < 3; nt++) {
                const unsigned* wb = uW + (nt * 8 + g) * WHS + ks * 8 + tg;
                MMA_TF32(ha[nt], a0, a1, a2, a3, wb[0], wb[4]);
            }
        }
#pragma unroll
        for (int nt = 0; nt < 3; nt++)
#pragma unroll
            for (int ci = 0; ci < 4; ci++) {
                int col = nt * 8 + (tg << 1) + (ci & 1);
                int r = mrowH + g + ((ci >> 1) << 3);
                int gr = rowbase + r;
                if (col < NACT)
                    pol[(size_t)gr * NACT + col] = ha[nt][ci] + bp[col];
                else if (col == NACT)
                    val[gr] = ha[nt][ci] + bv[0];
            }
    }
}

extern "C" void kernel_launch(void* const* d_in, const int* in_sizes, int n_in,
                              void* d_out, int out_size) {
    const float* x    = (const float*)d_in[0];
    const float* Wih0 = (const float*)d_in[1];
    // d_in[2] = Whh0: unused (h=0)
    const float* bih0 = (const float*)d_in[3];
    const float* bhh0 = (const float*)d_in[4];
    const float* Wih1 = (const float*)d_in[5];
    // d_in[6] = Whh1: unused (h=0)
    const float* bih1 = (const float*)d_in[7];
    const float* bhh1 = (const float*)d_in[8];
    const float* Wp   = (const float*)d_in[9];
    const float* bp   = (const float*)d_in[10];
    const float* Wv   = (const float*)d_in[11];
    const float* bv   = (const float*)d_in[12];
    float* out = (float*)d_out;

    cudaFuncSetAttribute(lstm_policy_kernel,
                         cudaFuncAttributeMaxDynamicSharedMemorySize, SMEM_BYTES);

    dim3 grid(BATCH / BM);
    dim3 block(NTHR);
    lstm_policy_kernel<<<grid, block, SMEM_BYTES>>>(
        x, Wih0, bih0, bhh0, Wih1, bih1, bhh1, Wp, bp, Wv, bv, out);
}

// round 14
// speedup vs baseline: 1.0162x; 1.0162x over previous
#include <cuda_runtime.h>
#include <cstdint>

#define BATCH 65536
#define INP 64
#define HID 128
#define NACT 16
#define BM 32
#define NTHR 256

// smem strides (floats); XS/HS ≡ 4 (mod 32), WS=20 -> verified conflict-free LDSM
#define XS 68
#define HS 132
#define WS 20
#define WHS 132

// Layout (floats): sH [32x132] at 0 (sX [32x68] ALIASED; x dead after chunk 3),
// 2-buffer gate-fused K=16 weight ring [384x20] each, head weights, biases.
#define RING_OFF 4224
#define BUF_FLOATS (384 * WS)                   // 7680
#define WH_OFF (RING_OFF + 2 * BUF_FLOATS)      // 19584
#define SB_OFF (WH_OFF + 24 * WHS)              // 22752
#define SMEM_FLOATS (SB_OFF + 6 * 128)          // 23520
#define SMEM_BYTES (SMEM_FLOATS * 4)            // 94080 B -> 2 CTAs/SM

__device__ __forceinline__ void cpa16(float* dst, const float* src) {
    unsigned u = (unsigned)__cvta_generic_to_shared(dst);
    asm volatile("cp.async.cg.shared.global [%0], [%1], 16;" ::"r"(u), "l"(src));
}
__device__ __forceinline__ void cpcommit() { asm volatile("cp.async.commit_group;"); }

__device__ __forceinline__ float htanh(float v) {
    float r;
    asm("tanh.approx.f32 %0, %1;" : "=f"(r) : "f"(v));
    return r;
}
__device__ __forceinline__ float fsig(float v) {
    return fmaf(htanh(0.5f * v), 0.5f, 0.5f);
}

#define MMA_TF32(d, a0, a1, a2, a3, b0, b1)                                     \
    asm volatile(                                                               \
        "mma.sync.aligned.m16n8k8.row.col.f32.tf32.tf32.f32 "                   \
        "{%0,%1,%2,%3},{%4,%5,%6,%7},{%8,%9},{%0,%1,%2,%3};"                    \
        : "+f"(d[0]), "+f"(d[1]), "+f"(d[2]), "+f"(d[3])                        \
        : "r"(a0), "r"(a1), "r"(a2), "r"(a3), "r"(b0), "r"(b1))

__device__ __forceinline__ void ldsm4(unsigned r[4], unsigned addr) {
    asm volatile("ldmatrix.sync.aligned.m8n8.x4.shared.b16 {%0,%1,%2,%3}, [%4];"
                 : "=r"(r[0]), "=r"(r[1]), "=r"(r[2]), "=r"(r[3])
                 : "r"(addr));
}

__global__ void __launch_bounds__(NTHR, 2)
lstm_policy_kernel(const float* __restrict__ x,
                   const float* __restrict__ Wih0,
                   const float* __restrict__ bih0,
                   const float* __restrict__ bhh0,
                   const float* __restrict__ Wih1,
                   const float* __restrict__ bih1,
                   const float* __restrict__ bhh1,
                   const float* __restrict__ Wp,
                   const float* __restrict__ bp,
                   const float* __restrict__ Wv,
                   const float* __restrict__ bv,
                   float* __restrict__ out) {
    extern __shared__ float sm[];
    float* sH = sm;              // [32][132] h0
    float* sX = sm;              // [32][68]  x, ALIASED (dead after chunk 3)
    float* sW = sm + RING_OFF;   // 2 x [384][20] ring
    float* sH1 = sm + RING_OFF;  // h1 plain [32][132] over dead ring buf0
    float* sWH = sm + WH_OFF;
    float* sB = sm + SB_OFF;

    const int tid = threadIdx.x;
    const int wid = tid >> 5, lane = tid & 31;
    const int g = lane >> 2, tg = lane & 3;
    // 8 warps, each owns a UNIQUE 16-out-col strip x 3 gates; 32 batch rows
    const int ncolW = wid * 16;
    const int rowbase = blockIdx.x * BM;

    // warp-private slab prefetch for chunk k (0..11): 3 gates x 16 rows x 16 K
    // = 192 f4. Only THIS warp reads these rows -> per-warp wait; NO barriers.
    auto prefSlab = [&](int k) {
        const float* W = (k < 4) ? Wih0 : Wih1;
        int ld = (k < 4) ? INP : HID;
        int koff = ((k < 4) ? k : (k - 4)) * 16;
        float* dst = sW + (k & 1) * BUF_FLOATS;
#pragma unroll
        for (int i = 0; i < 6; i++) {
            int idx = lane + i * 32;  // 192 f4 = 3 gates x 16 rows x 4 c4
            int gate = idx >> 6;
            int rem = idx & 63;
            int r = rem >> 2, c4 = rem & 3;
            int gbase = (gate == 0) ? 0 : (gate == 1 ? 256 : 384);
            int row = ncolW + r;
            cpa16(dst + (gate * 128 + row) * WS + c4 * 4,
                  W + (size_t)(gbase + row) * ld + koff + c4 * 4);
        }
    };

    // ---- prologue: G0 = {x, head weights}; G1 = {slab0} ----
    {
        const float* xs = x + (size_t)rowbase * INP;
#pragma unroll
        for (int i = 0; i < 2; i++) {
            int idx = tid + i * NTHR;  // 512 f4 (32 rows x 16)
            int r = idx >> 4;
            int c4 = idx & 15;
            cpa16(sX + r * XS + c4 * 4, xs + r * INP + c4 * 4);
        }
#pragma unroll
        for (int idx = tid; idx < 544; idx += NTHR) {  // strided! (R2 lesson)
            int r = idx >> 5, c4 = idx & 31;
            const float* srcp = (r < 16) ? (Wp + r * HID + c4 * 4) : (Wv + c4 * 4);
            cpa16(sWH + r * WHS + c4 * 4, srcp);
        }
        cpcommit();      // G0
        prefSlab(0);
        cpcommit();      // G1
    }

    // combined biases + zero-pad head rows 17..23
    if (tid < 128) {
        sB[tid] = bih0[tid] + bhh0[tid];
        sB[128 + tid] = bih0[256 + tid] + bhh0[256 + tid];
        sB[256 + tid] = bih0[384 + tid] + bhh0[384 + tid];
        sB[384 + tid] = bih1[tid] + bhh1[tid];
        sB[512 + tid] = bih1[256 + tid] + bhh1[256 + tid];
        sB[640 + tid] = bih1[384 + tid] + bhh1[384 + tid];
    }
#pragma unroll
    for (int idx = tid; idx < 7 * HID; idx += NTHR) {
        int r = 17 + idx / HID, c = idx % HID;
        sWH[r * WHS + c] = 0.f;
    }

    asm volatile("cp.async.wait_group 1;");  // G0 done (x, sWH); G1 may pend
    __syncthreads();  // BARRIER 1: x/sB/sWH visible

    // ---- LDSM addresses (verified mappings from R7-R9) ----
    const int j8 = lane & 7, sel = lane >> 3;
    const int arow = ((sel & 1) << 3) + j8;
    const int acol = (sel >> 1) << 2;
    const unsigned shBase = (unsigned)__cvta_generic_to_shared(sm);
    const unsigned swBase = shBase + RING_OFF * 4;
    const unsigned aX = shBase + (arow * XS + acol) * 4;
    const unsigned aH = shBase + (arow * HS + acol) * 4;
    // B ldsm4: bf[0]=nt0 b0, bf[1]=nt0 b1, bf[2]=nt1 b0, bf[3]=nt1 b1 (R7 map)
    const unsigned bO0 = ((ncolW + ((sel >> 1) << 3) + j8) * WS + ((sel & 1) << 2)) * 4;

    // gate-fused accumulators: [gate][mt][nt][ci] = 48 regs (R13-proven budget)
    float acc[3][2][2][4];
#pragma unroll
    for (int gt = 0; gt < 3; gt++)
#pragma unroll
        for (int mt = 0; mt < 2; mt++)
#pragma unroll
            for (int nt = 0; nt < 2; nt++)
#pragma unroll
                for (int ci = 0; ci < 4; ci++) acc[gt][mt][nt][ci] = 0.f;

    // one gate-fused K=16 chunk: 4 A-ldsm4 (reused by 3 gates) + 6 B-ldsm4, 24 MMA
    auto gemmChunk = [&](unsigned aBase, unsigned pitch, unsigned wbase) {
#pragma unroll
        for (int ks = 0; ks < 2; ks++) {
            unsigned af[2][4];
            ldsm4(af[0], aBase + ks * 32);
            ldsm4(af[1], aBase + pitch + ks * 32);
#pragma unroll
            for (int gt = 0; gt < 3; gt++) {
                unsigned bf[4];
                ldsm4(bf, wbase + gt * (128 * WS * 4) + bO0 + ks * 32);
#pragma unroll
                for (int mt = 0; mt < 2; mt++) {
                    MMA_TF32(acc[gt][mt][0], af[mt][0], af[mt][1], af[mt][2], af[mt][3], bf[0], bf[1]);
                    MMA_TF32(acc[gt][mt][1], af[mt][0], af[mt][1], af[mt][2], af[mt][3], bf[2], bf[3]);
                }
            }
        }
    };

    // single-pass epilogue from the 3 gate accs
    auto epi = [&](int L) {
#pragma unroll
        for (int mt = 0; mt < 2; mt++)
#pragma unroll
            for (int nt = 0; nt < 2; nt++)
#pragma unroll
                for (int ci = 0; ci < 4; ci++) {
                    int row = mt * 16 + g + ((ci >> 1) << 3);
                    int cc = ncolW + nt * 8 + (tg << 1) + (ci & 1);
                    float iv = acc[0][mt][nt][ci] + sB[L * 384 + cc];
                    float gv = acc[1][mt][nt][ci] + sB[L * 384 + 128 + cc];
                    float ov = acc[2][mt][nt][ci] + sB[L * 384 + 256 + cc];
                    float h = fsig(ov) * htanh(fsig(iv) * htanh(gv));
                    if (L == 0)
                        sH[row * HS + cc] = h;
                    else
                        sH1[row * HS + cc] = h;
                    acc[0][mt][nt][ci] = 0.f;
                    acc[1][mt][nt][ci] = 0.f;
                    acc[2][mt][nt][ci] = 0.f;
                }
    };

    const unsigned pX = 16 * XS * 4, pH = 16 * HS * 4;

    // ---- 12-chunk pipeline; slab k in buf k&1; per-warp waits only ----
    // iter k: pref(k+1) -> buf (k+1)&1 (this warp's reads ended at gemm k-1),
    // commit; wait_group 1 => G(k+1)=slab k complete; gemm k.
#pragma unroll
    for (int k = 0; k < 12; ++k) {
        if (k + 1 < 12) {
            prefSlab(k + 1);
            cpcommit();
            asm volatile("cp.async.wait_group 1;");
        } else {
            asm volatile("cp.async.wait_group 0;");
        }
        unsigned wb = swBase + (k & 1) * (BUF_FLOATS * 4);
        if (k < 4)
            gemmChunk(aX + k * 64, pX, wb);
        else
            gemmChunk(aH + (k - 4) * 64, pH, wb);

        if (k == 3) {  // layer boundary: h0 overwrites aliased sX
            __syncthreads();  // BARRIER 2: all warps done reading x
            epi(0);           // h0 -> sH
            __syncthreads();  // BARRIER 3: h0 visible to all warps
        }
    }

    __syncthreads();  // BARRIER 4: all warps done reading ring (h1 overwrites buf0)
    epi(1);           // h1 -> plain [32][132] over dead ring buf0
    __syncthreads();  // BARRIER 5: h1 visible

    // ---- heads on tensor cores (warps 0..1; proven code, 32 rows) ----
    float* pol = out;
    float* val = out + (size_t)BATCH * NACT;
    if (wid < 2) {
        float ha[3][4];
#pragma unroll
        for (int nt = 0; nt < 3; nt++)
#pragma unroll
            for (int ci = 0; ci < 4; ci++) ha[nt][ci] = 0.f;
        const unsigned* uA = (const unsigned*)sH1;
        const unsigned* uW = (const unsigned*)sWH;
        const int mrowH = wid * 16;
#pragma unroll
        for (int ks = 0; ks < 16; ks++) {
            const unsigned* bA = uA + (mrowH + g) * HS + ks * 8 + tg;
            unsigned a0 = bA[0], a1 = bA[8 * HS], a2 = bA[4], a3 = bA[8 * HS + 4];
#pragma unroll
            for (int nt = 0; nt < 3; nt++) {
                const unsigned* wb = uW + (nt * 8 + g) * WHS + ks * 8 + tg;
                MMA_TF32(ha[nt], a0, a1, a2, a3, wb[0], wb[4]);
            }
        }
#pragma unroll
        for (int nt = 0; nt < 3; nt++)
#pragma unroll
            for (int ci = 0; ci < 4; ci++) {
                int col = nt * 8 + (tg << 1) + (ci & 1);
                int r = mrowH + g + ((ci >> 1) << 3);
                int gr = rowbase + r;
                if (col < NACT)
                    pol[(size_t)gr * NACT + col] = ha[nt][ci] + bp[col];
                else if (col == NACT)
                    val[gr] = ha[nt][ci] + bv[0];
            }
    }
}

extern "C" void kernel_launch(void* const* d_in, const int* in_sizes, int n_in,
                              void* d_out, int out_size) {
    const float* x    = (const float*)d_in[0];
    const float* Wih0 = (const float*)d_in[1];
    // d_in[2] = Whh0: unused (h=0)
    const float* bih0 = (const float*)d_in[3];
    const float* bhh0 = (const float*)d_in[4];
    const float* Wih1 = (const float*)d_in[5];
    // d_in[6] = Whh1: unused (h=0)
    const float* bih1 = (const float*)d_in[7];
    const float* bhh1 = (const float*)d_in[8];
    const float* Wp   = (const float*)d_in[9];
    const float* bp   = (const float*)d_in[10];
    const float* Wv   = (const float*)d_in[11];
    const float* bv   = (const float*)d_in[12];
    float* out = (float*)d_out;

    cudaFuncSetAttribute(lstm_policy_kernel,
                         cudaFuncAttributeMaxDynamicSharedMemorySize, SMEM_BYTES);

    dim3 grid(BATCH / BM);
    dim3 block(NTHR);
    lstm_policy_kernel<<<grid, block, SMEM_BYTES>>>(
        x, Wih0, bih0, bhh0, Wih1, bih1, bhh1, Wp, bp, Wv, bv, out);
}

// round 15
// speedup vs baseline: 1.4390x; 1.4160x over previous
#include <cuda_runtime.h>
#include <cstdint>

#define BATCH 65536
#define INP 64
#define HID 128
#define NACT 16
#define BM 64
#define NTHR 256

// smem strides (floats); all ≡ 4 (mod 32) -> conflict-free LDSM row addressing
#define XS 68
#define HS 132
#define WS 36
#define WHS 132

// Layout (floats): sH [64x132] at 0 (sX [64x68] ALIASED; x dead after chunk 3),
// 2-buffer ring [256x36] each (ig slabs use 256 rows, o slabs 128), biases.
// h1 reuses buf0; head weights load into buf1 at the tail.
#define RING_OFF 8448
#define BUF_FLOATS (256 * 36)                   // 9216
#define SB_OFF (RING_OFF + 2 * BUF_FLOATS)      // 26880
#define SMEM_FLOATS (SB_OFF + 6 * 128)          // 27648
#define SMEM_BYTES (SMEM_FLOATS * 4)            // 110592 B -> 2 CTAs/SM

__device__ __forceinline__ void cpa16(float* dst, const float* src) {
    unsigned u = (unsigned)__cvta_generic_to_shared(dst);
    asm volatile("cp.async.cg.shared.global [%0], [%1], 16;" ::"r"(u), "l"(src));
}
__device__ __forceinline__ void cpcommit() { asm volatile("cp.async.commit_group;"); }

__device__ __forceinline__ float htanh(float v) {
    float r;
    asm("tanh.approx.f32 %0, %1;" : "=f"(r) : "f"(v));
    return r;
}
__device__ __forceinline__ float fsig(float v) {
    return fmaf(htanh(0.5f * v), 0.5f, 0.5f);
}

#define MMA_TF32(d, a0, a1, a2, a3, b0, b1)                                     \
    asm volatile(                                                               \
        "mma.sync.aligned.m16n8k8.row.col.f32.tf32.tf32.f32 "                   \
        "{%0,%1,%2,%3},{%4,%5,%6,%7},{%8,%9},{%0,%1,%2,%3};"                    \
        : "+f"(d[0]), "+f"(d[1]), "+f"(d[2]), "+f"(d[3])                        \
        : "r"(a0), "r"(a1), "r"(a2), "r"(a3), "r"(b0), "r"(b1))

__device__ __forceinline__ void ldsm4(unsigned r[4], unsigned addr) {
    asm volatile("ldmatrix.sync.aligned.m8n8.x4.shared.b16 {%0,%1,%2,%3}, [%4];"
                 : "=r"(r[0]), "=r"(r[1]), "=r"(r[2]), "=r"(r[3])
                 : "r"(addr));
}

__global__ void __launch_bounds__(NTHR, 2)
lstm_policy_kernel(const float* __restrict__ x,
                   const float* __restrict__ Wih0,
                   const float* __restrict__ bih0,
                   const float* __restrict__ bhh0,
                   const float* __restrict__ Wih1,
                   const float* __restrict__ bih1,
                   const float* __restrict__ bhh1,
                   const float* __restrict__ Wp,
                   const float* __restrict__ bp,
                   const float* __restrict__ Wv,
                   const float* __restrict__ bv,
                   float* __restrict__ out) {
    extern __shared__ float sm[];
    float* sH = sm;                         // [64][132] h0
    float* sX = sm;                         // [64][68]  x, ALIASED (dead after chunk 3)
    float* sW = sm + RING_OFF;              // 2 x [256][36] ring
    float* sH1 = sm + RING_OFF;             // h1 over dead buf0
    float* sWH = sm + RING_OFF + BUF_FLOATS;  // head weights over dead buf1 (tail)
    float* sB = sm + SB_OFF;

    const int tid = threadIdx.x;
    const int wid = tid >> 5, lane = tid & 31;
    const int g = lane >> 2, tg = lane & 3;
    // 8 warps, each owns a UNIQUE 16-out-col strip; A = all 64 batch rows (R9 tiling)
    const int ncolW = wid * 16;
    const int rowbase = blockIdx.x * BM;

    // warp-private slab prefetch for chunk k (0..11).
    // k=0,1: L0 ig (gates i+g, K-half k); k=2,3: L0 o; k=4..7: L1 ig; k=8..11: L1 o.
    // ig slab = 2 gates x 16 rows x 32K (256 f4); o slab = 16 rows x 32K (128 f4).
    // Only THIS warp reads its rows -> per-warp wait_group; NO barriers in loop.
    auto prefSlab = [&](int k) {
        const float* W = (k < 4) ? Wih0 : Wih1;
        int ld = (k < 4) ? INP : HID;
        int koff = ((k < 4) ? (k & 1) : ((k - 4) & 3)) * 32;
        float* dst = sW + (k & 1) * BUF_FLOATS;
        bool isIG = (k < 2) || (k >= 4 && k < 8);
        if (isIG) {
#pragma unroll
            for (int i = 0; i < 8; i++) {
                int idx = lane + i * 32;  // 256 f4
                int gt = idx >> 7;        // 0: gate i, 1: gate g
                int rem = idx & 127;
                int r = rem >> 3, c4 = rem & 7;
                int row = ncolW + r;
                cpa16(dst + (gt * 128 + row) * WS + c4 * 4,
                      W + (size_t)((gt ? 256 : 0) + row) * ld + koff + c4 * 4);
            }
        } else {
#pragma unroll
            for (int i = 0; i < 4; i++) {
                int idx = lane + i * 32;  // 128 f4
                int r = idx >> 3, c4 = idx & 7;
                int row = ncolW + r;
                cpa16(dst + row * WS + c4 * 4,
                      W + (size_t)(384 + row) * ld + koff + c4 * 4);
            }
        }
    };

    // ---- prologue: G0 = {x}; G1 = {slab0} ----
    {
        const float* xs = x + (size_t)rowbase * INP;
#pragma unroll
        for (int i = 0; i < 4; i++) {
            int idx = tid + i * NTHR;  // 1024 f4 (64 rows x 16)
            int r = idx >> 4;
            int c4 = idx & 15;
            cpa16(sX + r * XS + c4 * 4, xs + r * INP + c4 * 4);
        }
        cpcommit();  // G0
        prefSlab(0);
        cpcommit();  // G1
    }

    // combined biases (plain stores; covered by barrier 1)
    if (tid < 128) {
        sB[tid] = bih0[tid] + bhh0[tid];
        sB[128 + tid] = bih0[256 + tid] + bhh0[256 + tid];
        sB[256 + tid] = bih0[384 + tid] + bhh0[384 + tid];
        sB[384 + tid] = bih1[tid] + bhh1[tid];
        sB[512 + tid] = bih1[256 + tid] + bhh1[256 + tid];
        sB[640 + tid] = bih1[384 + tid] + bhh1[384 + tid];
    }

    asm volatile("cp.async.wait_group 1;");  // G0 done (x); G1 may pend
    __syncthreads();  // BARRIER 1: x/sB visible

    // ---- LDSM addresses (verified mapping from R7-R9) ----
    const int j8 = lane & 7, sel = lane >> 3;
    const int arow = ((sel & 1) << 3) + j8;
    const int acol = (sel >> 1) << 2;
    const unsigned shBase = (unsigned)__cvta_generic_to_shared(sm);
    const unsigned swBase = shBase + RING_OFF * 4;
    const unsigned aX = shBase + (arow * XS + acol) * 4;
    const unsigned aH = shBase + (arow * HS + acol) * 4;
    // B ldsm4 covers rows [ncolW, ncolW+16) x 8K: bf = {nt0 b0, nt0 b1, nt1 b0, nt1 b1}
    const unsigned bO0 = ((ncolW + ((sel >> 1) << 3) + j8) * WS + ((sel & 1) << 2)) * 4;

    // acc[0]=gate i (later reused for gate o), acc[1]=gate g; sc = staged c
    float acc[2][4][2][4], sc[4][2][4];
#pragma unroll
    for (int gt = 0; gt < 2; gt++)
#pragma unroll
        for (int mt = 0; mt < 4; mt++)
#pragma unroll
            for (int nt = 0; nt < 2; nt++)
#pragma unroll
                for (int ci = 0; ci < 4; ci++) acc[gt][mt][nt][ci] = 0.f;

    // ig chunk: A loaded once per ks, reused by gates i AND g (the A-traffic cut)
    auto gemmIG = [&](unsigned aBase, unsigned pitch, unsigned wbase) {
#pragma unroll
        for (int ks = 0; ks < 4; ks++) {
            unsigned af[4][4];
#pragma unroll
            for (int mt = 0; mt < 4; mt++) ldsm4(af[mt], aBase + mt * pitch + ks * 32);
#pragma unroll
            for (int gt = 0; gt < 2; gt++) {
                unsigned bf[4];
                ldsm4(bf, wbase + gt * (128 * WS * 4) + bO0 + ks * 32);
#pragma unroll
                for (int mt = 0; mt < 4; mt++) {
                    MMA_TF32(acc[gt][mt][0], af[mt][0], af[mt][1], af[mt][2], af[mt][3], bf[0], bf[1]);
                    MMA_TF32(acc[gt][mt][1], af[mt][0], af[mt][1], af[mt][2], af[mt][3], bf[2], bf[3]);
                }
            }
        }
    };
    // o chunk: accumulates into acc[0] (freed by cStage)
    auto gemmO = [&](unsigned aBase, unsigned pitch, unsigned wbase) {
#pragma unroll
        for (int ks = 0; ks < 4; ks++) {
            unsigned bf[4];
            ldsm4(bf, wbase + bO0 + ks * 32);
#pragma unroll
            for (int mt = 0; mt < 4; mt++) {
                unsigned af[4];
                ldsm4(af, aBase + mt * pitch + ks * 32);
                MMA_TF32(acc[0][mt][0], af[0], af[1], af[2], af[3], bf[0], bf[1]);
                MMA_TF32(acc[0][mt][1], af[0], af[1], af[2], af[3], bf[2], bf[3]);
            }
        }
    };

    // c = sigmoid(i)*tanh(g) -> sc; free both accs (same op order as R9 epiSig+epiG)
    auto cStage = [&](int L) {
#pragma unroll
        for (int mt = 0; mt < 4; mt++)
#pragma unroll
            for (int nt = 0; nt < 2; nt++)
#pragma unroll
                for (int ci = 0; ci < 4; ci++) {
                    int cc = ncolW + nt * 8 + (tg << 1) + (ci & 1);
                    float iv = acc[0][mt][nt][ci] + sB[L * 384 + cc];
                    float gv = acc[1][mt][nt][ci] + sB[L * 384 + 128 + cc];
                    sc[mt][nt][ci] = fsig(iv) * htanh(gv);
                    acc[0][mt][nt][ci] = 0.f;
                    acc[1][mt][nt][ci] = 0.f;
                }
    };
    // h = sigmoid(o)*tanh(c) -> smem
    auto epiH = [&](int L) {
#pragma unroll
        for (int mt = 0; mt < 4; mt++)
#pragma unroll
            for (int nt = 0; nt < 2; nt++)
#pragma unroll
                for (int ci = 0; ci < 4; ci++) {
                    int row = mt * 16 + g + ((ci >> 1) << 3);
                    int cc = ncolW + nt * 8 + (tg << 1) + (ci & 1);
                    float ov = acc[0][mt][nt][ci] + sB[L * 384 + 256 + cc];
                    float h = fsig(ov) * htanh(sc[mt][nt][ci]);
                    if (L == 0)
                        sH[row * HS + cc] = h;
                    else
                        sH1[row * HS + cc] = h;
                    acc[0][mt][nt][ci] = 0.f;
                }
    };

    const unsigned pX = 16 * XS * 4, pH = 16 * HS * 4;

    // ---- 12-chunk pipeline; slab k in buf k&1; per-warp waits only ----
#pragma unroll
    for (int k = 0; k < 12; ++k) {
        if (k + 1 < 12) {
            prefSlab(k + 1);  // buf (k+1)&1: this warp's reads ended at gemm(k-1)
            cpcommit();
            asm volatile("cp.async.wait_group 1;");  // slab k complete
        } else {
            asm volatile("cp.async.wait_group 0;");
        }
        unsigned wb = swBase + (k & 1) * (BUF_FLOATS * 4);
        if (k < 2)
            gemmIG(aX + k * 128, pX, wb);
        else if (k < 4)
            gemmO(aX + (k - 2) * 128, pX, wb);
        else if (k < 8)
            gemmIG(aH + (k - 4) * 128, pH, wb);
        else
            gemmO(aH + (k - 8) * 128, pH, wb);

        if (k == 1) cStage(0);
        else if (k == 3) {        // layer boundary: h0 overwrites aliased sX
            __syncthreads();      // BARRIER 2: all warps done reading x
            epiH(0);              // h0 -> sH
            __syncthreads();      // BARRIER 3: h0 visible to all warps
        } else if (k == 7) cStage(1);
    }

    __syncthreads();  // BARRIER 4: all ring reads done (h1/headW overwrite bufs)

    // head weights -> dead buf1 region (overlap with h1 epilogue)
#pragma unroll
    for (int idx = tid; idx < 544; idx += NTHR) {  // strided! (R2 lesson)
        int r = idx >> 5, c4 = idx & 31;
        const float* srcp = (r < 16) ? (Wp + r * HID + c4 * 4) : (Wv + c4 * 4);
        cpa16(sWH + r * WHS + c4 * 4, srcp);
    }
    cpcommit();
    epiH(1);  // h1 -> dead buf0
#pragma unroll
    for (int idx = tid; idx < 7 * HID; idx += NTHR) {  // zero-pad head rows 17..23
        int r = 17 + idx / HID, c = idx % HID;
        sWH[r * WHS + c] = 0.f;
    }
    asm volatile("cp.async.wait_group 0;");
    __syncthreads();  // BARRIER 5: h1 + head weights visible

    // ---- heads on tensor cores (warps 0..3; proven code) ----
    float* pol = out;
    float* val = out + (size_t)BATCH * NACT;
    if (wid < 4) {
        float ha[3][4];
#pragma unroll
        for (int nt = 0; nt < 3; nt++)
#pragma unroll
            for (int ci = 0; ci < 4; ci++) ha[nt][ci] = 0.f;
        const unsigned* uA = (const unsigned*)sH1;
        const unsigned* uW = (const unsigned*)sWH;
        const int mrowH = wid * 16;
#pragma unroll
        for (int ks = 0; ks < 16; ks++) {
            const unsigned* bA = uA + (mrowH + g) * HS + ks * 8 + tg;
            unsigned a0 = bA[0], a1 = bA[8 * HS], a2 = bA[4], a3 = bA[8 * HS + 4];
#pragma unroll
            for (int nt = 0; nt < 3; nt++) {
                const unsigned* wb = uW + (nt * 8 + g) * WHS + ks * 8 + tg;
                MMA_TF32(ha[nt], a0, a1, a2, a3, wb[0], wb[4]);
            }
        }
#pragma unroll
        for (int nt = 0; nt < 3; nt++)
#pragma unroll
            for (int ci = 0; ci < 4; ci++) {
                int col = nt * 8 + (tg << 1) + (ci & 1);
                int r = mrowH + g + ((ci >> 1) << 3);
                int gr = rowbase + r;
                if (col < NACT)
                    pol[(size_t)gr * NACT + col] = ha[nt][ci] + bp[col];
                else if (col == NACT)
                    val[gr] = ha[nt][ci] + bv[0];
            }
    }
}

extern "C" void kernel_launch(void* const* d_in, const int* in_sizes, int n_in,
                              void* d_out, int out_size) {
    const float* x    = (const float*)d_in[0];
    const float* Wih0 = (const float*)d_in[1];
    // d_in[2] = Whh0: unused (h=0)
    const float* bih0 = (const float*)d_in[3];
    const float* bhh0 = (const float*)d_in[4];
    const float* Wih1 = (const float*)d_in[5];
    // d_in[6] = Whh1: unused (h=0)
    const float* bih1 = (const float*)d_in[7];
    const float* bhh1 = (const float*)d_in[8];
    const float* Wp   = (const float*)d_in[9];
    const float* bp   = (const float*)d_in[10];
    const float* Wv   = (const float*)d_in[11];
    const float* bv   = (const float*)d_in[12];
    float* out = (float*)d_out;

    cudaFuncSetAttribute(lstm_policy_kernel,
                         cudaFuncAttributeMaxDynamicSharedMemorySize, SMEM_BYTES);

    dim3 grid(BATCH / BM);
    dim3 block(NTHR);
    lstm_policy_kernel<<<grid, block, SMEM_BYTES>>>(
        x, Wih0, bih0, bhh0, Wih1, bih1, bhh1, Wp, bp, Wv, bv, out);
}